// round 14
// baseline (speedup 1.0000x reference)
#include <cuda_runtime.h>
#include <math.h>

// Problem constants
#define NBLK 128
#define TPB  512
#define BB   64
#define TT   256
#define DD   512
#define WW   256
#define FF   256
#define G4D  2048

// -------- dynamic smem layout (float offsets) --------
#define OFF_W0   0         // 12288: 768 rows x 16c (0..255 M0, 256..767 R0)
#define OFF_W1   12288     // 16384: 1024 rows x 16c (0..511 K1, 512..1023 R1)
#define OFF_WOUT 28672     // 1024: 512 x 2
#define OFF_CVEC 29696     // 1024: cvec TRANSPOSED [c][b] (16 x 64)
#define OFF_BIAS 30720     // 64
#define OFF_CST  30784     // 512: c state [layer][b][q]
#define OFF_MBAR 31296     // 16 mbarriers x 8B = 32 floats (16B aligned)
#define OFF_WORK 31328     // staging 16w x (2x512)=16384 ALIASED w/ partials 16 x 1152 = 18432
#define OFF_ZBUF 49760     // 1088: compact z [cc][b] stride 68
#define SMEM_FLOATS 50848
#define SMEM_BYTES  (SMEM_FLOATS * 4)   // 203392 B

// -------- persistent device state (transposed activations: [k][b]) --------
__device__ float g_hT[2][2][DD][BB];   // [parity][layer][d][b]
__device__ float g_prevT[WW][BB];      // [w][b]
__device__ float g_cbias[BB][DD];
__device__ unsigned int g_arrive;
__device__ unsigned int g_gen;
__device__ unsigned int g_flags[NBLK];

__device__ __forceinline__ float sigf(float x) { return 1.0f / (1.0f + expf(-x)); }

// ---- packed f32x2 helpers ----
__device__ __forceinline__ unsigned long long ffma2(unsigned long long a,
                                                    unsigned long long b,
                                                    unsigned long long c) {
    unsigned long long d;
    asm("fma.rn.f32x2 %0, %1, %2, %3;" : "=l"(d) : "l"(a), "l"(b), "l"(c));
    return d;
}
__device__ __forceinline__ unsigned long long addf2(unsigned long long a,
                                                    unsigned long long b) {
    unsigned long long d;
    asm("add.rn.f32x2 %0, %1, %2;" : "=l"(d) : "l"(a), "l"(b));
    return d;
}
__device__ __forceinline__ unsigned long long pack2(float x) {
    unsigned long long d;
    asm("mov.b64 %0, {%1, %1};" : "=l"(d) : "f"(x));
    return d;
}
__device__ __forceinline__ float lo2(unsigned long long v) {
    return __uint_as_float((unsigned)(v & 0xffffffffull));
}
__device__ __forceinline__ float hi2(unsigned long long v) {
    return __uint_as_float((unsigned)(v >> 32));
}

// ---- smem/mbarrier/TMA helpers ----
__device__ __forceinline__ unsigned smem_u32(const void* p) {
    unsigned r;
    asm("{ .reg .u64 t; cvta.to.shared.u64 t, %1; cvt.u32.u64 %0, t; }"
        : "=r"(r) : "l"(p));
    return r;
}
__device__ __forceinline__ void mbar_init(unsigned a, unsigned cnt) {
    asm volatile("mbarrier.init.shared.b64 [%0], %1;" :: "r"(a), "r"(cnt) : "memory");
}
__device__ __forceinline__ void mbar_expect_tx(unsigned a, unsigned bytes) {
    asm volatile("mbarrier.arrive.expect_tx.shared.b64 _, [%0], %1;"
                 :: "r"(a), "r"(bytes) : "memory");
}
__device__ __forceinline__ void bulk_g2s(unsigned saddr, const void* g,
                                         unsigned bytes, unsigned mbar) {
    asm volatile("cp.async.bulk.shared::cta.global.mbarrier::complete_tx::bytes "
                 "[%0], [%1], %2, [%3];"
                 :: "r"(saddr), "l"(g), "r"(bytes), "r"(mbar) : "memory");
}
__device__ __forceinline__ void mbar_wait(unsigned a, unsigned parity) {
    asm volatile(
        "{\n\t"
        ".reg .pred P1;\n\t"
        "WAIT_LOOP_%=:\n\t"
        "mbarrier.try_wait.parity.acquire.cta.shared::cta.b64 P1, [%0], %1, 0x989680;\n\t"
        "@P1 bra.uni WAIT_DONE_%=;\n\t"
        "bra.uni WAIT_LOOP_%=;\n\t"
        "WAIT_DONE_%=:\n\t"
        "}"
        :: "r"(a), "r"(parity) : "memory");
}

// atomic barrier (init only)
__device__ __forceinline__ void grid_barrier_atomic() {
    __syncthreads();
    if (threadIdx.x == 0) {
        __threadfence();
        unsigned gen = *((volatile unsigned int*)&g_gen);
        unsigned old = atomicAdd(&g_arrive, 1);
        if (old == NBLK - 1) {
            g_arrive = 0;
            __threadfence();
            atomicAdd(&g_gen, 1);
        } else {
            while (*((volatile unsigned int*)&g_gen) == gen) { }
        }
        __threadfence();
    }
    __syncthreads();
}

// flag barrier (per-CTA release store + parallel poll)
__device__ __forceinline__ void flag_barrier(unsigned seq) {
    __syncthreads();
    if (threadIdx.x == 0) {
        asm volatile("st.release.gpu.u32 [%0], %1;"
                     :: "l"(&g_flags[blockIdx.x]), "r"(seq) : "memory");
    }
    bool ok = true;
    if (threadIdx.x < NBLK) {
        unsigned v;
        asm volatile("ld.acquire.gpu.u32 %0, [%1];"
                     : "=r"(v) : "l"(&g_flags[threadIdx.x]) : "memory");
        ok = ((int)(v - seq) >= 0);
    }
    while (!__syncthreads_and(ok)) {
        if (threadIdx.x < NBLK) {
            unsigned v;
            asm volatile("ld.acquire.gpu.u32 %0, [%1];"
                         : "=r"(v) : "l"(&g_flags[threadIdx.x]) : "memory");
            ok = ((int)(v - seq) >= 0);
        }
    }
}

// ============================================================================
// LSTM layer phase. Each warp = one K-slice covering the FULL 64b x 16c tile.
// A staged via cp.async.bulk (2KB chunks, double-buffered).
// Thread tile 4b x 8c: bg = lane&15 (b = bg*4..+3), cg = lane>>4 (c = cg*8..+7).
// Both cg halves read the SAME A address (broadcast dedup).
// Partials stored as float4 per (warp, col, b-group); gather is 16x LDS.128 +
// packed f32x2 adds with bias/cvec folded in; compact zbuf feeds gate stage.
// ============================================================================
__device__ __noinline__ void phase_L(
    const float* __restrict__ gsrc, int nch, int wrow0,
    const float* __restrict__ smW, const float* __restrict__ smBias,
    const float* __restrict__ smCvecT,
    float* __restrict__ smC, float* __restrict__ gHout,
    float* __restrict__ sm, unsigned par0)
{
    const int tid = threadIdx.x;
    const int w = tid >> 5, lane = tid & 31;
    const int bg = lane & 15, cg = lane >> 4;
    const int nbase = blockIdx.x * 4;

    const unsigned smu = smem_u32(sm);
    const unsigned mbar = smu + (OFF_MBAR + w * 2) * 4;
    const unsigned dbase = smu + (OFF_WORK + w * 1024) * 4;

    unsigned long long acc2[16];
#pragma unroll
    for (int m = 0; m < 16; m++) acc2[m] = 0ull;

    // issue chunk 0
    if (lane == 0) {
        mbar_expect_tx(mbar, 2048);
        bulk_g2s(dbase, gsrc, 2048, mbar);
    }

    for (int ch = 0; ch < nch; ch++) {
        mbar_wait(mbar, (par0 + ch) & 1);
        if (ch + 1 < nch && lane == 0) {
            mbar_expect_tx(mbar, 2048);
            bulk_g2s(dbase + ((ch + 1) & 1) * 2048, gsrc + (ch + 1) * 512, 2048, mbar);
        }
        __syncwarp();
        const float* mb = sm + OFF_WORK + w * 1024 + (ch & 1) * 512;
        const float* wr = smW + (wrow0 + ch * 8) * 16 + cg * 8;
#pragma unroll
        for (int j = 0; j < 8; j++) {
            ulonglong2 aA = *(const ulonglong2*)(mb + j * 64 + bg * 4);  // 4 b's
            float4 wv0 = *(const float4*)(wr + j * 16);
            float4 wv1 = *(const float4*)(wr + j * 16 + 4);
            unsigned long long w0 = pack2(wv0.x), w1 = pack2(wv0.y);
            unsigned long long w2 = pack2(wv0.z), w3 = pack2(wv0.w);
            unsigned long long w4 = pack2(wv1.x), w5 = pack2(wv1.y);
            unsigned long long w6 = pack2(wv1.z), w7 = pack2(wv1.w);
            acc2[0]  = ffma2(aA.x, w0, acc2[0]);
            acc2[1]  = ffma2(aA.x, w1, acc2[1]);
            acc2[2]  = ffma2(aA.x, w2, acc2[2]);
            acc2[3]  = ffma2(aA.x, w3, acc2[3]);
            acc2[4]  = ffma2(aA.x, w4, acc2[4]);
            acc2[5]  = ffma2(aA.x, w5, acc2[5]);
            acc2[6]  = ffma2(aA.x, w6, acc2[6]);
            acc2[7]  = ffma2(aA.x, w7, acc2[7]);
            acc2[8]  = ffma2(aA.y, w0, acc2[8]);
            acc2[9]  = ffma2(aA.y, w1, acc2[9]);
            acc2[10] = ffma2(aA.y, w2, acc2[10]);
            acc2[11] = ffma2(aA.y, w3, acc2[11]);
            acc2[12] = ffma2(aA.y, w4, acc2[12]);
            acc2[13] = ffma2(aA.y, w5, acc2[13]);
            acc2[14] = ffma2(aA.y, w6, acc2[14]);
            acc2[15] = ffma2(aA.y, w7, acc2[15]);
        }
    }

    // partials: per warp region [16 cc][68 pad] float4 at bg*4; components = 4 b's
    float* rb = sm + OFF_WORK;
    __syncthreads();
#pragma unroll
    for (int jj = 0; jj < 8; jj++) {
        unsigned long long vx = acc2[jj];        // b idx 0,1
        unsigned long long vy = acc2[8 + jj];    // b idx 2,3
        float4 v;
        v.x = lo2(vx); v.y = hi2(vx); v.z = lo2(vy); v.w = hi2(vy);
        *(float4*)(rb + w * 1152 + (cg * 8 + jj) * 68 + bg * 4) = v;
    }
    __syncthreads();

    // gather: tid<256, (bgp, cc) sums 16 warp-slices as packed f32x2,
    // folds in bias + cvecT, writes compact zbuf[cc][b].
    if (tid < 256) {
        const int bgp = tid >> 4, cc = tid & 15;
        const float* src = rb + cc * 68 + bgp * 4;
        ulonglong2 acc = *(const ulonglong2*)(src);
#pragma unroll
        for (int kk = 1; kk < 16; kk++) {
            ulonglong2 v = *(const ulonglong2*)(src + kk * 1152);
            acc.x = addf2(acc.x, v.x);
            acc.y = addf2(acc.y, v.y);
        }
        unsigned long long bb = pack2(smBias[cc]);
        acc.x = addf2(acc.x, bb);
        acc.y = addf2(acc.y, bb);
        if (smCvecT) {
            ulonglong2 cv = *(const ulonglong2*)(smCvecT + cc * 64 + bgp * 4);
            acc.x = addf2(acc.x, cv.x);
            acc.y = addf2(acc.y, cv.y);
        }
        *(ulonglong2*)(sm + OFF_ZBUF + cc * 68 + bgp * 4) = acc;
    }
    __syncthreads();

    // gate stage: tid<256 handles (b, q)
    if (tid < 256) {
        const int b = tid >> 2, q = tid & 3;
        const int n = nbase + q;
        float zi = sm[OFF_ZBUF + q * 68 + b];
        float zf = sm[OFF_ZBUF + (4 + q) * 68 + b];
        float zg = sm[OFF_ZBUF + (8 + q) * 68 + b];
        float zo = sm[OFF_ZBUF + (12 + q) * 68 + b];
        float co = smC[b * 4 + q];
        float ig = sigf(zi), fg = sigf(zf), gg = tanhf(zg), og = sigf(zo);
        float cn = fg * co + ig * gg;
        float hn = og * tanhf(cn);
        smC[b * 4 + q] = cn;
        __stcg(&gHout[n * BB + b], hn);   // transposed write [d][b]
    }
}

// ============================================================================
// P3: out = sigmoid(h1T @ W_out + b_out). CTA covers 2 cols. 16 warps x 32k.
// lane: bg = lane&15 (b = bg*4..+3), cg = lane>>4 (1 col each). 2 f32x2 accs.
// ============================================================================
__device__ __noinline__ void phase_p3(
    const float* __restrict__ gsrc,
    const float* __restrict__ smWO, const float* __restrict__ smBias,
    float* __restrict__ dout, int t, float* __restrict__ sm, unsigned par0)
{
    const int tid = threadIdx.x;
    const int w = tid >> 5, lane = tid & 31;
    const int bg = lane & 15, cg = lane >> 4;
    const int cbase = blockIdx.x * 2;
    const int wrow0 = w * 32;

    const unsigned smu = smem_u32(sm);
    const unsigned mbar = smu + (OFF_MBAR + w * 2) * 4;
    const unsigned dbase = smu + (OFF_WORK + w * 1024) * 4;

    unsigned long long acc2[2] = {0ull, 0ull};

    if (lane == 0) {
        mbar_expect_tx(mbar, 2048);
        bulk_g2s(dbase, gsrc + w * 32 * BB, 2048, mbar);
    }

    for (int ch = 0; ch < 4; ch++) {
        mbar_wait(mbar, (par0 + ch) & 1);
        if (ch + 1 < 4 && lane == 0) {
            mbar_expect_tx(mbar, 2048);
            bulk_g2s(dbase + ((ch + 1) & 1) * 2048,
                     gsrc + w * 32 * BB + (ch + 1) * 512, 2048, mbar);
        }
        __syncwarp();
        const float* mb = sm + OFF_WORK + w * 1024 + (ch & 1) * 512;
#pragma unroll
        for (int j = 0; j < 8; j++) {
            ulonglong2 aA = *(const ulonglong2*)(mb + j * 64 + bg * 4);
            unsigned long long wp = pack2(smWO[(wrow0 + ch * 8 + j) * 2 + cg]);
            acc2[0] = ffma2(aA.x, wp, acc2[0]);
            acc2[1] = ffma2(aA.y, wp, acc2[1]);
        }
    }

    // partials: per warp [32 lanes][5]; b = bg*4 + m
    float* rb = sm + OFF_WORK;
    __syncthreads();
    rb[w * 160 + lane * 5 + 0] = lo2(acc2[0]);
    rb[w * 160 + lane * 5 + 1] = hi2(acc2[0]);
    rb[w * 160 + lane * 5 + 2] = lo2(acc2[1]);
    rb[w * 160 + lane * 5 + 3] = hi2(acc2[1]);
    __syncthreads();

    if (tid < 128) {
        const int b = tid >> 1, cl = tid & 1;
        const int lane_g = cl * 16 + (b >> 2), m = b & 3;
        const float* base = rb + lane_g * 5 + m;
        float s = base[0];
#pragma unroll
        for (int kk = 1; kk < 16; kk++) s += base[kk * 160];
        float v = sigf(s + smBias[32 + cl]);
        dout[(b * TT + t) * WW + cbase + cl] = v;
        __stcg(&g_prevT[cbase + cl][b], v);   // transposed write
    }
}

// ============================================================================
// Persistent kernel
// ============================================================================
__global__ void __launch_bounds__(TPB, 1)
lstm_persistent_kernel(const float* __restrict__ inputs,
                       const float* __restrict__ rand_prev,
                       const float* __restrict__ init_h,
                       const float* __restrict__ init_c,
                       const float* __restrict__ W_in,
                       const float* __restrict__ b_in,
                       const float* __restrict__ kernels,
                       const float* __restrict__ rec_kernels,
                       const float* __restrict__ biases,
                       const float* __restrict__ W_out,
                       const float* __restrict__ b_out,
                       float* __restrict__ out) {
    extern __shared__ float sm[];
    const int tid = threadIdx.x;
    const int w = tid >> 5;
    const int nbase = blockIdx.x * 4;
    const int cbase = blockIdx.x * 2;
    const int gt = blockIdx.x * TPB + tid;
    const int gstride = NBLK * TPB;

    // mbarrier init (one per warp)
    if (tid < 16) mbar_init(smem_u32(sm) + (OFF_MBAR + tid * 2) * 4, 1);

    // ---- weight preload into smem ----
    for (int idx = tid; idx < 512 * 16; idx += TPB) {
        int row = idx >> 4, c = idx & 15, g = c >> 2, q = c & 3;
        sm[OFF_W0 + (256 + row) * 16 + c] = rec_kernels[row * G4D + g * DD + nbase + q];
    }
    for (int idx = tid; idx < 1024 * 16; idx += TPB) {
        int row = idx >> 4, c = idx & 15, g = c >> 2, q = c & 3;
        float v = (row < 512)
            ? kernels[DD * G4D + row * G4D + g * DD + nbase + q]
            : rec_kernels[DD * G4D + (row - 512) * G4D + g * DD + nbase + q];
        sm[OFF_W1 + idx] = v;
    }
    for (int idx = tid; idx < 512 * 2; idx += TPB) {
        int k = idx >> 1, c = idx & 1;
        sm[OFF_WOUT + idx] = W_out[k * WW + cbase + c];
    }
    if (tid < 16) {
        int g = tid >> 2, q = tid & 3;
        sm[OFF_BIAS + tid] = biases[g * DD + nbase + q];
    } else if (tid < 32) {
        int c = tid - 16, g = c >> 2, q = c & 3;
        sm[OFF_BIAS + tid] = biases[G4D + g * DD + nbase + q];
    } else if (tid < 34) {
        sm[OFF_BIAS + tid] = b_out[cbase + tid - 32];
    }
    for (int idx = tid; idx < 512; idx += TPB) {
        int l = idx >> 8, r = idx & 255, b = r >> 2, q = r & 3;
        sm[OFF_CST + idx] = init_c[(l * BB + b) * DD + nbase + q];
    }

    // ---- global state init (transposed; every launch — graph replays) ----
    if (tid == 0) g_flags[blockIdx.x] = 0;
    for (int i = gt; i < 2 * DD * BB; i += gstride) {
        int l = i >> 15, d = (i >> 6) & (DD - 1), b = i & 63;
        g_hT[0][l][d][b] = init_h[(l * BB + b) * DD + d];
    }
    for (int i = gt; i < WW * BB; i += gstride) {
        int k = i >> 6, b = i & 63;
        g_prevT[k][b] = rand_prev[b * WW + k];
    }
    for (int i = gt; i < BB * DD; i += gstride) {
        const int b = i >> 9, dc = i & (DD - 1);
        const float* cn = inputs + b * FF;
        float s = b_in[dc];
#pragma unroll 4
        for (int k = 0; k < FF; k++)
            s = fmaf(cn[k], W_in[(WW + k) * DD + dc], s);
        (&g_cbias[0][0])[i] = s;
    }
    grid_barrier_atomic();

    // ---- M0 = W_in[0:256] @ K0 -> smem W0 rows 0..255 ----
    for (int idx = tid; idx < 256 * 16; idx += TPB) {
        int r = idx >> 4, c = idx & 15, g = c >> 2, q = c & 3;
        const int col = g * DD + nbase + q;
        float s = 0.0f;
#pragma unroll 8
        for (int d = 0; d < DD; d++)
            s = fmaf(W_in[r * DD + d], kernels[d * G4D + col], s);
        sm[OFF_W0 + r * 16 + c] = s;
    }
    // ---- cvecT = (cbias @ K0)^T stored [c][b] for vectorized epilogue ----
    for (int idx = tid; idx < BB * 16; idx += TPB) {
        int c = idx >> 6, b = idx & 63, g = c >> 2, q = c & 3;
        const int col = g * DD + nbase + q;
        float s = 0.0f;
#pragma unroll 8
        for (int d = 0; d < DD; d++)
            s = fmaf(g_cbias[b][d], kernels[d * G4D + col], s);
        sm[OFF_CVEC + c * 64 + b] = s;
    }
    __syncthreads();

    // per-warp K-slice parameters
    const int l0_nch   = (w < 8) ? 4 : 8;                       // 32k or 64k
    const int l0_wrow0 = (w < 8) ? (w * 32) : (256 + (w - 8) * 64);

    unsigned seq = 0, mcount = 0;
    for (int t = 0; t < TT; t++) {
        const int p = t & 1;

        // L0: A = [prevT (256k) | h0T prev (512k)]
        {
            const float* gsrc = (w < 8)
                ? (&g_prevT[0][0] + w * 32 * BB)
                : (&g_hT[p][0][0][0] + (w - 8) * 64 * BB);
            phase_L(gsrc, l0_nch, l0_wrow0,
                    sm + OFF_W0, sm + OFF_BIAS, sm + OFF_CVEC,
                    sm + OFF_CST, &g_hT[1 - p][0][0][0], sm, mcount);
            mcount += l0_nch;
        }
        flag_barrier(++seq);

        // L1: A = [h0T new (512k) | h1T prev (512k)], uniform 64k/warp
        {
            const float* gsrc = (w < 8)
                ? (&g_hT[1 - p][0][0][0] + w * 64 * BB)
                : (&g_hT[p][1][0][0] + (w - 8) * 64 * BB);
            phase_L(gsrc, 8, w * 64,
                    sm + OFF_W1, sm + OFF_BIAS + 16, (const float*)0,
                    sm + OFF_CST + 256, &g_hT[1 - p][1][0][0], sm, mcount);
            mcount += 8;
        }
        flag_barrier(++seq);

        // P3: h1T new @ W_out
        phase_p3(&g_hT[1 - p][1][0][0], sm + OFF_WOUT, sm + OFF_BIAS,
                 out, t, sm, mcount);
        mcount += 4;
        flag_barrier(++seq);
    }
}

extern "C" void kernel_launch(void* const* d_in, const int* in_sizes, int n_in,
                              void* d_out, int out_size) {
    const float* inputs      = (const float*)d_in[0];
    const float* rand_prev   = (const float*)d_in[1];
    const float* init_h      = (const float*)d_in[2];
    const float* init_c      = (const float*)d_in[3];
    const float* W_in        = (const float*)d_in[4];
    const float* b_in        = (const float*)d_in[5];
    const float* kernels     = (const float*)d_in[6];
    const float* rec_kernels = (const float*)d_in[7];
    const float* biases      = (const float*)d_in[8];
    const float* W_out       = (const float*)d_in[9];
    const float* b_out       = (const float*)d_in[10];
    float* out = (float*)d_out;

    static int attr_done = 0;
    if (!attr_done) {
        cudaFuncSetAttribute(lstm_persistent_kernel,
                             cudaFuncAttributeMaxDynamicSharedMemorySize, SMEM_BYTES);
        attr_done = 1;
    }
    lstm_persistent_kernel<<<NBLK, TPB, SMEM_BYTES>>>(
        inputs, rand_prev, init_h, init_c, W_in, b_in, kernels, rec_kernels,
        biases, W_out, b_out, out);
}

// round 15
// speedup vs baseline: 1.3040x; 1.3040x over previous
#include <cuda_runtime.h>
#include <math.h>

// Problem constants
#define NBLK 128
#define TPB  512
#define BB   64
#define TT   256
#define DD   512
#define WW   256
#define FF   256
#define G4D  2048

// -------- dynamic smem layout (float offsets) --------
#define OFF_W0   0         // 12288: 768 rows x 16c (0..255 M0, 256..767 R0)
#define OFF_W1   12288     // 16384: 1024 rows x 16c (0..511 K1, 512..1023 R1)
#define OFF_WOUT 28672     // 1024: 512 x 2
#define OFF_CVEC 29696     // 1024: 64b x 16c
#define OFF_BIAS 30720     // 64
#define OFF_CST  30784     // 512: c state [layer][b][q]
#define OFF_MBAR 31296     // 16 mbarriers x 8B = 32 floats (16B aligned)
#define OFF_WORK 31328     // 16896: staging 16w x (2x512) aliased w/ partials 16w x (32x33)
#define SMEM_FLOATS (31328 + 16896)
#define SMEM_BYTES  (SMEM_FLOATS * 4)

// -------- persistent device state (transposed activations: [k][b]) --------
__device__ float g_hT[2][2][DD][BB];   // [parity][layer][d][b]
__device__ float g_prevT[WW][BB];      // [w][b]
__device__ float g_cbias[BB][DD];
__device__ unsigned int g_arrive;
__device__ unsigned int g_gen;
__device__ unsigned int g_flags[NBLK];

__device__ __forceinline__ float sigf(float x) { return 1.0f / (1.0f + expf(-x)); }

// ---- packed f32x2 helpers ----
__device__ __forceinline__ unsigned long long ffma2(unsigned long long a,
                                                    unsigned long long b,
                                                    unsigned long long c) {
    unsigned long long d;
    asm("fma.rn.f32x2 %0, %1, %2, %3;" : "=l"(d) : "l"(a), "l"(b), "l"(c));
    return d;
}
__device__ __forceinline__ unsigned long long pack2(float x) {
    unsigned long long d;
    asm("mov.b64 %0, {%1, %1};" : "=l"(d) : "f"(x));
    return d;
}
__device__ __forceinline__ float lo2(unsigned long long v) {
    return __uint_as_float((unsigned)(v & 0xffffffffull));
}
__device__ __forceinline__ float hi2(unsigned long long v) {
    return __uint_as_float((unsigned)(v >> 32));
}

// ---- smem/mbarrier/TMA helpers ----
__device__ __forceinline__ unsigned smem_u32(const void* p) {
    unsigned r;
    asm("{ .reg .u64 t; cvta.to.shared.u64 t, %1; cvt.u32.u64 %0, t; }"
        : "=r"(r) : "l"(p));
    return r;
}
__device__ __forceinline__ void mbar_init(unsigned a, unsigned cnt) {
    asm volatile("mbarrier.init.shared.b64 [%0], %1;" :: "r"(a), "r"(cnt) : "memory");
}
__device__ __forceinline__ void mbar_expect_tx(unsigned a, unsigned bytes) {
    asm volatile("mbarrier.arrive.expect_tx.shared.b64 _, [%0], %1;"
                 :: "r"(a), "r"(bytes) : "memory");
}
__device__ __forceinline__ void bulk_g2s(unsigned saddr, const void* g,
                                         unsigned bytes, unsigned mbar) {
    asm volatile("cp.async.bulk.shared::cta.global.mbarrier::complete_tx::bytes "
                 "[%0], [%1], %2, [%3];"
                 :: "r"(saddr), "l"(g), "r"(bytes), "r"(mbar) : "memory");
}
__device__ __forceinline__ void mbar_wait(unsigned a, unsigned parity) {
    asm volatile(
        "{\n\t"
        ".reg .pred P1;\n\t"
        "WAIT_LOOP_%=:\n\t"
        "mbarrier.try_wait.parity.acquire.cta.shared::cta.b64 P1, [%0], %1, 0x989680;\n\t"
        "@P1 bra.uni WAIT_DONE_%=;\n\t"
        "bra.uni WAIT_LOOP_%=;\n\t"
        "WAIT_DONE_%=:\n\t"
        "}"
        :: "r"(a), "r"(parity) : "memory");
}

// atomic barrier (init only)
__device__ __forceinline__ void grid_barrier_atomic() {
    __syncthreads();
    if (threadIdx.x == 0) {
        __threadfence();
        unsigned gen = *((volatile unsigned int*)&g_gen);
        unsigned old = atomicAdd(&g_arrive, 1);
        if (old == NBLK - 1) {
            g_arrive = 0;
            __threadfence();
            atomicAdd(&g_gen, 1);
        } else {
            while (*((volatile unsigned int*)&g_gen) == gen) { }
        }
        __threadfence();
    }
    __syncthreads();
}

// flag barrier (per-CTA release store + parallel poll)
__device__ __forceinline__ void flag_barrier(unsigned seq) {
    __syncthreads();
    if (threadIdx.x == 0) {
        asm volatile("st.release.gpu.u32 [%0], %1;"
                     :: "l"(&g_flags[blockIdx.x]), "r"(seq) : "memory");
    }
    bool ok = true;
    if (threadIdx.x < NBLK) {
        unsigned v;
        asm volatile("ld.acquire.gpu.u32 %0, [%1];"
                     : "=r"(v) : "l"(&g_flags[threadIdx.x]) : "memory");
        ok = ((int)(v - seq) >= 0);
    }
    while (!__syncthreads_and(ok)) {
        if (threadIdx.x < NBLK) {
            unsigned v;
            asm volatile("ld.acquire.gpu.u32 %0, [%1];"
                         : "=r"(v) : "l"(&g_flags[threadIdx.x]) : "memory");
            ok = ((int)(v - seq) >= 0);
        }
    }
}

// ============================================================================
// LSTM layer phase. Each warp = one K-slice covering the FULL 64b x 16c tile.
// A staged via cp.async.bulk (2KB chunks, double-buffered).
// Thread tile 4b x 8c: bg = lane&15 (b = bg*4..+3), cg = lane>>4 (c = cg*8..+7).
// Both cg halves read the SAME A address (broadcast dedup: 2 wf per A-row
// instead of 8) -> halves L1 wavefront pressure vs the 8b x 4c tile.
// ============================================================================
__device__ __noinline__ void phase_L(
    const float* __restrict__ gsrc, int nch, int wrow0,
    const float* __restrict__ smW, const float* __restrict__ smBias,
    const float* __restrict__ smCvec,
    float* __restrict__ smC, float* __restrict__ gHout,
    float* __restrict__ sm, unsigned par0)
{
    const int tid = threadIdx.x;
    const int w = tid >> 5, lane = tid & 31;
    const int bg = lane & 15, cg = lane >> 4;
    const int nbase = blockIdx.x * 4;

    const unsigned smu = smem_u32(sm);
    const unsigned mbar = smu + (OFF_MBAR + w * 2) * 4;
    const unsigned dbase = smu + (OFF_WORK + w * 1024) * 4;

    unsigned long long acc2[16];
#pragma unroll
    for (int m = 0; m < 16; m++) acc2[m] = 0ull;

    // issue chunk 0
    if (lane == 0) {
        mbar_expect_tx(mbar, 2048);
        bulk_g2s(dbase, gsrc, 2048, mbar);
    }

    for (int ch = 0; ch < nch; ch++) {
        mbar_wait(mbar, (par0 + ch) & 1);
        if (ch + 1 < nch && lane == 0) {
            mbar_expect_tx(mbar, 2048);
            bulk_g2s(dbase + ((ch + 1) & 1) * 2048, gsrc + (ch + 1) * 512, 2048, mbar);
        }
        __syncwarp();
        const float* mb = sm + OFF_WORK + w * 1024 + (ch & 1) * 512;
        const float* wr = smW + (wrow0 + ch * 8) * 16 + cg * 8;
#pragma unroll
        for (int j = 0; j < 8; j++) {
            ulonglong2 aA = *(const ulonglong2*)(mb + j * 64 + bg * 4);  // 4 b's
            float4 wv0 = *(const float4*)(wr + j * 16);
            float4 wv1 = *(const float4*)(wr + j * 16 + 4);
            unsigned long long w0 = pack2(wv0.x), w1 = pack2(wv0.y);
            unsigned long long w2 = pack2(wv0.z), w3 = pack2(wv0.w);
            unsigned long long w4 = pack2(wv1.x), w5 = pack2(wv1.y);
            unsigned long long w6 = pack2(wv1.z), w7 = pack2(wv1.w);
            acc2[0]  = ffma2(aA.x, w0, acc2[0]);
            acc2[1]  = ffma2(aA.x, w1, acc2[1]);
            acc2[2]  = ffma2(aA.x, w2, acc2[2]);
            acc2[3]  = ffma2(aA.x, w3, acc2[3]);
            acc2[4]  = ffma2(aA.x, w4, acc2[4]);
            acc2[5]  = ffma2(aA.x, w5, acc2[5]);
            acc2[6]  = ffma2(aA.x, w6, acc2[6]);
            acc2[7]  = ffma2(aA.x, w7, acc2[7]);
            acc2[8]  = ffma2(aA.y, w0, acc2[8]);
            acc2[9]  = ffma2(aA.y, w1, acc2[9]);
            acc2[10] = ffma2(aA.y, w2, acc2[10]);
            acc2[11] = ffma2(aA.y, w3, acc2[11]);
            acc2[12] = ffma2(aA.y, w4, acc2[12]);
            acc2[13] = ffma2(aA.y, w5, acc2[13]);
            acc2[14] = ffma2(aA.y, w6, acc2[14]);
            acc2[15] = ffma2(aA.y, w7, acc2[15]);
        }
    }

    // partials: region per warp [32 lanes][33]
    // lane holds b = bg*4 + idx (idx: accpair/hilo), c = cg*8 + jj
    // store at m = jj*4 + idx
    float* rb = sm + OFF_WORK;
    __syncthreads();
#pragma unroll
    for (int jj = 0; jj < 8; jj++) {
        unsigned long long vx = acc2[jj];        // b idx 0,1
        unsigned long long vy = acc2[8 + jj];    // b idx 2,3
        rb[w * 1056 + lane * 33 + jj * 4 + 0] = lo2(vx);
        rb[w * 1056 + lane * 33 + jj * 4 + 1] = hi2(vx);
        rb[w * 1056 + lane * 33 + jj * 4 + 2] = lo2(vy);
        rb[w * 1056 + lane * 33 + jj * 4 + 3] = hi2(vy);
    }
    __syncthreads();

    // gather + gate epilogue: tid<256 handles (b, q)
    if (tid < 256) {
        const int b = tid >> 2, q = tid & 3;
        const int n = nbase + q;
        const int bgp = b >> 2, idx = b & 3;
        float z[4];
#pragma unroll
        for (int gate = 0; gate < 4; gate++) {
            const int cc = gate * 4 + q;
            const int lane_g = (cc >> 3) * 16 + bgp;
            const int m = (cc & 7) * 4 + idx;
            const float* base = rb + lane_g * 33 + m;
            float s = base[0];
#pragma unroll
            for (int kk = 1; kk < 16; kk++) s += base[kk * 1056];
            z[gate] = s;
        }
        float cvi = 0.0f, cvf = 0.0f, cvg = 0.0f, cvo = 0.0f;
        if (smCvec) {
            cvi = smCvec[b * 16 + q];
            cvf = smCvec[b * 16 + 4 + q];
            cvg = smCvec[b * 16 + 8 + q];
            cvo = smCvec[b * 16 + 12 + q];
        }
        float zi = z[0] + smBias[q]      + cvi;
        float zf = z[1] + smBias[4 + q]  + cvf;
        float zg = z[2] + smBias[8 + q]  + cvg;
        float zo = z[3] + smBias[12 + q] + cvo;
        float co = smC[b * 4 + q];
        float ig = sigf(zi), fg = sigf(zf), gg = tanhf(zg), og = sigf(zo);
        float cn = fg * co + ig * gg;
        float hn = og * tanhf(cn);
        smC[b * 4 + q] = cn;
        __stcg(&gHout[n * BB + b], hn);   // transposed write [d][b]
    }
}

// ============================================================================
// P3: out = sigmoid(h1T @ W_out + b_out). CTA covers 2 cols. 16 warps x 32k.
// lane: bg = lane&15 (b = bg*4..+3), cg = lane>>4 (1 col each). 2 f32x2 accs.
// ============================================================================
__device__ __noinline__ void phase_p3(
    const float* __restrict__ gsrc,
    const float* __restrict__ smWO, const float* __restrict__ smBias,
    float* __restrict__ dout, int t, float* __restrict__ sm, unsigned par0)
{
    const int tid = threadIdx.x;
    const int w = tid >> 5, lane = tid & 31;
    const int bg = lane & 15, cg = lane >> 4;
    const int cbase = blockIdx.x * 2;
    const int wrow0 = w * 32;

    const unsigned smu = smem_u32(sm);
    const unsigned mbar = smu + (OFF_MBAR + w * 2) * 4;
    const unsigned dbase = smu + (OFF_WORK + w * 1024) * 4;

    unsigned long long acc2[2] = {0ull, 0ull};

    if (lane == 0) {
        mbar_expect_tx(mbar, 2048);
        bulk_g2s(dbase, gsrc + w * 32 * BB, 2048, mbar);
    }

    for (int ch = 0; ch < 4; ch++) {
        mbar_wait(mbar, (par0 + ch) & 1);
        if (ch + 1 < 4 && lane == 0) {
            mbar_expect_tx(mbar, 2048);
            bulk_g2s(dbase + ((ch + 1) & 1) * 2048,
                     gsrc + w * 32 * BB + (ch + 1) * 512, 2048, mbar);
        }
        __syncwarp();
        const float* mb = sm + OFF_WORK + w * 1024 + (ch & 1) * 512;
#pragma unroll
        for (int j = 0; j < 8; j++) {
            ulonglong2 aA = *(const ulonglong2*)(mb + j * 64 + bg * 4);
            unsigned long long wp = pack2(smWO[(wrow0 + ch * 8 + j) * 2 + cg]);
            acc2[0] = ffma2(aA.x, wp, acc2[0]);
            acc2[1] = ffma2(aA.y, wp, acc2[1]);
        }
    }

    // partials: per warp [32 lanes][5]; b = bg*4 + m
    float* rb = sm + OFF_WORK;
    __syncthreads();
    rb[w * 160 + lane * 5 + 0] = lo2(acc2[0]);
    rb[w * 160 + lane * 5 + 1] = hi2(acc2[0]);
    rb[w * 160 + lane * 5 + 2] = lo2(acc2[1]);
    rb[w * 160 + lane * 5 + 3] = hi2(acc2[1]);
    __syncthreads();

    if (tid < 128) {
        const int b = tid >> 1, cl = tid & 1;
        const int lane_g = cl * 16 + (b >> 2), m = b & 3;
        const float* base = rb + lane_g * 5 + m;
        float s = base[0];
#pragma unroll
        for (int kk = 1; kk < 16; kk++) s += base[kk * 160];
        float v = sigf(s + smBias[32 + cl]);
        dout[(b * TT + t) * WW + cbase + cl] = v;
        __stcg(&g_prevT[cbase + cl][b], v);   // transposed write
    }
}

// ============================================================================
// Persistent kernel
// ============================================================================
__global__ void __launch_bounds__(TPB, 1)
lstm_persistent_kernel(const float* __restrict__ inputs,
                       const float* __restrict__ rand_prev,
                       const float* __restrict__ init_h,
                       const float* __restrict__ init_c,
                       const float* __restrict__ W_in,
                       const float* __restrict__ b_in,
                       const float* __restrict__ kernels,
                       const float* __restrict__ rec_kernels,
                       const float* __restrict__ biases,
                       const float* __restrict__ W_out,
                       const float* __restrict__ b_out,
                       float* __restrict__ out) {
    extern __shared__ float sm[];
    const int tid = threadIdx.x;
    const int w = tid >> 5;
    const int nbase = blockIdx.x * 4;
    const int cbase = blockIdx.x * 2;
    const int gt = blockIdx.x * TPB + tid;
    const int gstride = NBLK * TPB;

    // mbarrier init (one per warp)
    if (tid < 16) mbar_init(smem_u32(sm) + (OFF_MBAR + tid * 2) * 4, 1);

    // ---- weight preload into smem ----
    for (int idx = tid; idx < 512 * 16; idx += TPB) {
        int row = idx >> 4, c = idx & 15, g = c >> 2, q = c & 3;
        sm[OFF_W0 + (256 + row) * 16 + c] = rec_kernels[row * G4D + g * DD + nbase + q];
    }
    for (int idx = tid; idx < 1024 * 16; idx += TPB) {
        int row = idx >> 4, c = idx & 15, g = c >> 2, q = c & 3;
        float v = (row < 512)
            ? kernels[DD * G4D + row * G4D + g * DD + nbase + q]
            : rec_kernels[DD * G4D + (row - 512) * G4D + g * DD + nbase + q];
        sm[OFF_W1 + idx] = v;
    }
    for (int idx = tid; idx < 512 * 2; idx += TPB) {
        int k = idx >> 1, c = idx & 1;
        sm[OFF_WOUT + idx] = W_out[k * WW + cbase + c];
    }
    if (tid < 16) {
        int g = tid >> 2, q = tid & 3;
        sm[OFF_BIAS + tid] = biases[g * DD + nbase + q];
    } else if (tid < 32) {
        int c = tid - 16, g = c >> 2, q = c & 3;
        sm[OFF_BIAS + tid] = biases[G4D + g * DD + nbase + q];
    } else if (tid < 34) {
        sm[OFF_BIAS + tid] = b_out[cbase + tid - 32];
    }
    for (int idx = tid; idx < 512; idx += TPB) {
        int l = idx >> 8, r = idx & 255, b = r >> 2, q = r & 3;
        sm[OFF_CST + idx] = init_c[(l * BB + b) * DD + nbase + q];
    }

    // ---- global state init (transposed; every launch — graph replays) ----
    if (tid == 0) g_flags[blockIdx.x] = 0;
    for (int i = gt; i < 2 * DD * BB; i += gstride) {
        int l = i >> 15, d = (i >> 6) & (DD - 1), b = i & 63;
        g_hT[0][l][d][b] = init_h[(l * BB + b) * DD + d];
    }
    for (int i = gt; i < WW * BB; i += gstride) {
        int k = i >> 6, b = i & 63;
        g_prevT[k][b] = rand_prev[b * WW + k];
    }
    for (int i = gt; i < BB * DD; i += gstride) {
        const int b = i >> 9, dc = i & (DD - 1);
        const float* cn = inputs + b * FF;
        float s = b_in[dc];
#pragma unroll 4
        for (int k = 0; k < FF; k++)
            s = fmaf(cn[k], W_in[(WW + k) * DD + dc], s);
        (&g_cbias[0][0])[i] = s;
    }
    grid_barrier_atomic();

    // ---- M0 = W_in[0:256] @ K0 -> smem W0 rows 0..255 ----
    for (int idx = tid; idx < 256 * 16; idx += TPB) {
        int r = idx >> 4, c = idx & 15, g = c >> 2, q = c & 3;
        const int col = g * DD + nbase + q;
        float s = 0.0f;
#pragma unroll 8
        for (int d = 0; d < DD; d++)
            s = fmaf(W_in[r * DD + d], kernels[d * G4D + col], s);
        sm[OFF_W0 + r * 16 + c] = s;
    }
    // ---- cvec = cbias @ K0 ----
    for (int idx = tid; idx < BB * 16; idx += TPB) {
        int b = idx >> 4, c = idx & 15, g = c >> 2, q = c & 3;
        const int col = g * DD + nbase + q;
        float s = 0.0f;
#pragma unroll 8
        for (int d = 0; d < DD; d++)
            s = fmaf(g_cbias[b][d], kernels[d * G4D + col], s);
        sm[OFF_CVEC + b * 16 + c] = s;
    }
    __syncthreads();

    // per-warp K-slice parameters
    const int l0_nch   = (w < 8) ? 4 : 8;                       // 32k or 64k
    const int l0_wrow0 = (w < 8) ? (w * 32) : (256 + (w - 8) * 64);

    unsigned seq = 0, mcount = 0;
    for (int t = 0; t < TT; t++) {
        const int p = t & 1;

        // L0: A = [prevT (256k) | h0T prev (512k)]
        {
            const float* gsrc = (w < 8)
                ? (&g_prevT[0][0] + w * 32 * BB)
                : (&g_hT[p][0][0][0] + (w - 8) * 64 * BB);
            phase_L(gsrc, l0_nch, l0_wrow0,
                    sm + OFF_W0, sm + OFF_BIAS, sm + OFF_CVEC,
                    sm + OFF_CST, &g_hT[1 - p][0][0][0], sm, mcount);
            mcount += l0_nch;
        }
        flag_barrier(++seq);

        // L1: A = [h0T new (512k) | h1T prev (512k)], uniform 64k/warp
        {
            const float* gsrc = (w < 8)
                ? (&g_hT[1 - p][0][0][0] + w * 64 * BB)
                : (&g_hT[p][1][0][0] + (w - 8) * 64 * BB);
            phase_L(gsrc, 8, w * 64,
                    sm + OFF_W1, sm + OFF_BIAS + 16, (const float*)0,
                    sm + OFF_CST + 256, &g_hT[1 - p][1][0][0], sm, mcount);
            mcount += 8;
        }
        flag_barrier(++seq);

        // P3: h1T new @ W_out
        phase_p3(&g_hT[1 - p][1][0][0], sm + OFF_WOUT, sm + OFF_BIAS,
                 out, t, sm, mcount);
        mcount += 4;
        flag_barrier(++seq);
    }
}

extern "C" void kernel_launch(void* const* d_in, const int* in_sizes, int n_in,
                              void* d_out, int out_size) {
    const float* inputs      = (const float*)d_in[0];
    const float* rand_prev   = (const float*)d_in[1];
    const float* init_h      = (const float*)d_in[2];
    const float* init_c      = (const float*)d_in[3];
    const float* W_in        = (const float*)d_in[4];
    const float* b_in        = (const float*)d_in[5];
    const float* kernels     = (const float*)d_in[6];
    const float* rec_kernels = (const float*)d_in[7];
    const float* biases      = (const float*)d_in[8];
    const float* W_out       = (const float*)d_in[9];
    const float* b_out       = (const float*)d_in[10];
    float* out = (float*)d_out;

    static int attr_done = 0;
    if (!attr_done) {
        cudaFuncSetAttribute(lstm_persistent_kernel,
                             cudaFuncAttributeMaxDynamicSharedMemorySize, SMEM_BYTES);
        attr_done = 1;
    }
    lstm_persistent_kernel<<<NBLK, TPB, SMEM_BYTES>>>(
        inputs, rand_prev, init_h, init_c, W_in, b_in, kernels, rec_kernels,
        biases, W_out, b_out, out);
}

// round 16
// speedup vs baseline: 1.4089x; 1.0804x over previous
#include <cuda_runtime.h>
#include <math.h>

// Problem constants
#define NBLK 128
#define TPB  512
#define BB   64
#define TT   256
#define DD   512
#define WW   256
#define FF   256
#define G4D  2048

// -------- dynamic smem layout (float offsets) --------
#define OFF_W0   0         // 12288: 768 rows x 16c (0..255 M0, 256..767 R0)
#define OFF_W1   12288     // 16384: 1024 rows x 16c (0..511 K1, 512..1023 R1)
#define OFF_WOUT 28672     // 1024: 512 x 2
#define OFF_CVEC 29696     // 1024: 64b x 16c
#define OFF_BIAS 30720     // 64
#define OFF_CST  30784     // 512: c state [layer][b][q]
#define OFF_MBAR 31296     // 16 mbarriers x 8B = 32 floats (16B aligned)
#define OFF_WORK 31328     // 16896: staging 16w x (2x512) aliased w/ partials 16w x (32x33)
#define SMEM_FLOATS (31328 + 16896)
#define SMEM_BYTES  (SMEM_FLOATS * 4)

// -------- persistent device state (transposed activations: [k][b]) --------
__device__ float g_hT[2][2][DD][BB];   // [parity][layer][d][b]
__device__ float g_prevT[WW][BB];      // [w][b]
__device__ float g_cbias[BB][DD];
__device__ unsigned int g_arrive;
__device__ unsigned int g_gen;
__device__ unsigned int g_flags[NBLK];

__device__ __forceinline__ float sigf(float x) { return 1.0f / (1.0f + expf(-x)); }

// ---- packed f32x2 helpers ----
__device__ __forceinline__ unsigned long long ffma2(unsigned long long a,
                                                    unsigned long long b,
                                                    unsigned long long c) {
    unsigned long long d;
    asm("fma.rn.f32x2 %0, %1, %2, %3;" : "=l"(d) : "l"(a), "l"(b), "l"(c));
    return d;
}
__device__ __forceinline__ unsigned long long pack2(float x) {
    unsigned long long d;
    asm("mov.b64 %0, {%1, %1};" : "=l"(d) : "f"(x));
    return d;
}
__device__ __forceinline__ float lo2(unsigned long long v) {
    return __uint_as_float((unsigned)(v & 0xffffffffull));
}
__device__ __forceinline__ float hi2(unsigned long long v) {
    return __uint_as_float((unsigned)(v >> 32));
}

// ---- smem/mbarrier/TMA helpers ----
__device__ __forceinline__ unsigned smem_u32(const void* p) {
    unsigned r;
    asm("{ .reg .u64 t; cvta.to.shared.u64 t, %1; cvt.u32.u64 %0, t; }"
        : "=r"(r) : "l"(p));
    return r;
}
__device__ __forceinline__ void mbar_init(unsigned a, unsigned cnt) {
    asm volatile("mbarrier.init.shared.b64 [%0], %1;" :: "r"(a), "r"(cnt) : "memory");
}
__device__ __forceinline__ void mbar_expect_tx(unsigned a, unsigned bytes) {
    asm volatile("mbarrier.arrive.expect_tx.shared.b64 _, [%0], %1;"
                 :: "r"(a), "r"(bytes) : "memory");
}
__device__ __forceinline__ void bulk_g2s(unsigned saddr, const void* g,
                                         unsigned bytes, unsigned mbar) {
    asm volatile("cp.async.bulk.shared::cta.global.mbarrier::complete_tx::bytes "
                 "[%0], [%1], %2, [%3];"
                 :: "r"(saddr), "l"(g), "r"(bytes), "r"(mbar) : "memory");
}
__device__ __forceinline__ void mbar_wait(unsigned a, unsigned parity) {
    asm volatile(
        "{\n\t"
        ".reg .pred P1;\n\t"
        "WAIT_LOOP_%=:\n\t"
        "mbarrier.try_wait.parity.acquire.cta.shared::cta.b64 P1, [%0], %1, 0x989680;\n\t"
        "@P1 bra.uni WAIT_DONE_%=;\n\t"
        "bra.uni WAIT_LOOP_%=;\n\t"
        "WAIT_DONE_%=:\n\t"
        "}"
        :: "r"(a), "r"(parity) : "memory");
}

// atomic barrier (init only)
__device__ __forceinline__ void grid_barrier_atomic() {
    __syncthreads();
    if (threadIdx.x == 0) {
        __threadfence();
        unsigned gen = *((volatile unsigned int*)&g_gen);
        unsigned old = atomicAdd(&g_arrive, 1);
        if (old == NBLK - 1) {
            g_arrive = 0;
            __threadfence();
            atomicAdd(&g_gen, 1);
        } else {
            while (*((volatile unsigned int*)&g_gen) == gen) { }
        }
        __threadfence();
    }
    __syncthreads();
}

// flag barrier (per-CTA release store + parallel poll)
__device__ __forceinline__ void flag_barrier(unsigned seq) {
    __syncthreads();
    if (threadIdx.x == 0) {
        asm volatile("st.release.gpu.u32 [%0], %1;"
                     :: "l"(&g_flags[blockIdx.x]), "r"(seq) : "memory");
    }
    bool ok = true;
    if (threadIdx.x < NBLK) {
        unsigned v;
        asm volatile("ld.acquire.gpu.u32 %0, [%1];"
                     : "=r"(v) : "l"(&g_flags[threadIdx.x]) : "memory");
        ok = ((int)(v - seq) >= 0);
    }
    while (!__syncthreads_and(ok)) {
        if (threadIdx.x < NBLK) {
            unsigned v;
            asm volatile("ld.acquire.gpu.u32 %0, [%1];"
                         : "=r"(v) : "l"(&g_flags[threadIdx.x]) : "memory");
            ok = ((int)(v - seq) >= 0);
        }
    }
}

// ============================================================================
// LSTM layer phase. Each warp = one K-slice covering the FULL 64b x 16c tile.
// A staged via cp.async.bulk (2KB chunks, double-buffered).
// Chunk ch < chB comes from srcA, else srcB (prevT/h0T boundary in L0;
// srcA==srcB for L1). Thread tile 4b x 8c with broadcast-dedup A reads.
// Staging/mbarrier/epilogue structure byte-identical to the R9 champion.
// ============================================================================
__device__ __noinline__ void phase_L(
    const float* __restrict__ srcA, const float* __restrict__ srcB, int chB,
    int nch, int wrow0,
    const float* __restrict__ smW, const float* __restrict__ smBias,
    const float* __restrict__ smCvec,
    float* __restrict__ smC, float* __restrict__ gHout,
    float* __restrict__ sm, unsigned par0)
{
    const int tid = threadIdx.x;
    const int w = tid >> 5, lane = tid & 31;
    const int bg = lane & 15, cg = lane >> 4;
    const int nbase = blockIdx.x * 4;

    const unsigned smu = smem_u32(sm);
    const unsigned mbar = smu + (OFF_MBAR + w * 2) * 4;
    const unsigned dbase = smu + (OFF_WORK + w * 1024) * 4;

    unsigned long long acc2[16];
#pragma unroll
    for (int m = 0; m < 16; m++) acc2[m] = 0ull;

    // issue chunk 0
    if (lane == 0) {
        const float* s0 = (0 < chB) ? srcA : srcB;
        mbar_expect_tx(mbar, 2048);
        bulk_g2s(dbase, s0, 2048, mbar);
    }

    for (int ch = 0; ch < nch; ch++) {
        mbar_wait(mbar, (par0 + ch) & 1);
        if (ch + 1 < nch && lane == 0) {
            const int c1 = ch + 1;
            const float* s1 = (c1 < chB) ? srcA + c1 * 512 : srcB + (c1 - chB) * 512;
            mbar_expect_tx(mbar, 2048);
            bulk_g2s(dbase + (c1 & 1) * 2048, s1, 2048, mbar);
        }
        __syncwarp();
        const float* mb = sm + OFF_WORK + w * 1024 + (ch & 1) * 512;
        const float* wr = smW + (wrow0 + ch * 8) * 16 + cg * 8;
#pragma unroll
        for (int j = 0; j < 8; j++) {
            ulonglong2 aA = *(const ulonglong2*)(mb + j * 64 + bg * 4);  // 4 b's
            float4 wv0 = *(const float4*)(wr + j * 16);
            float4 wv1 = *(const float4*)(wr + j * 16 + 4);
            unsigned long long w0 = pack2(wv0.x), w1 = pack2(wv0.y);
            unsigned long long w2 = pack2(wv0.z), w3 = pack2(wv0.w);
            unsigned long long w4 = pack2(wv1.x), w5 = pack2(wv1.y);
            unsigned long long w6 = pack2(wv1.z), w7 = pack2(wv1.w);
            acc2[0]  = ffma2(aA.x, w0, acc2[0]);
            acc2[1]  = ffma2(aA.x, w1, acc2[1]);
            acc2[2]  = ffma2(aA.x, w2, acc2[2]);
            acc2[3]  = ffma2(aA.x, w3, acc2[3]);
            acc2[4]  = ffma2(aA.x, w4, acc2[4]);
            acc2[5]  = ffma2(aA.x, w5, acc2[5]);
            acc2[6]  = ffma2(aA.x, w6, acc2[6]);
            acc2[7]  = ffma2(aA.x, w7, acc2[7]);
            acc2[8]  = ffma2(aA.y, w0, acc2[8]);
            acc2[9]  = ffma2(aA.y, w1, acc2[9]);
            acc2[10] = ffma2(aA.y, w2, acc2[10]);
            acc2[11] = ffma2(aA.y, w3, acc2[11]);
            acc2[12] = ffma2(aA.y, w4, acc2[12]);
            acc2[13] = ffma2(aA.y, w5, acc2[13]);
            acc2[14] = ffma2(aA.y, w6, acc2[14]);
            acc2[15] = ffma2(aA.y, w7, acc2[15]);
        }
    }

    // partials: region per warp [32 lanes][33]
    // lane holds b = bg*4 + idx (idx: accpair/hilo), c = cg*8 + jj
    // store at m = jj*4 + idx
    float* rb = sm + OFF_WORK;
    __syncthreads();
#pragma unroll
    for (int jj = 0; jj < 8; jj++) {
        unsigned long long vx = acc2[jj];        // b idx 0,1
        unsigned long long vy = acc2[8 + jj];    // b idx 2,3
        rb[w * 1056 + lane * 33 + jj * 4 + 0] = lo2(vx);
        rb[w * 1056 + lane * 33 + jj * 4 + 1] = hi2(vx);
        rb[w * 1056 + lane * 33 + jj * 4 + 2] = lo2(vy);
        rb[w * 1056 + lane * 33 + jj * 4 + 3] = hi2(vy);
    }
    __syncthreads();

    // gather + gate epilogue: tid<256 handles (b, q)
    if (tid < 256) {
        const int b = tid >> 2, q = tid & 3;
        const int n = nbase + q;
        const int bgp = b >> 2, idx = b & 3;
        float z[4];
#pragma unroll
        for (int gate = 0; gate < 4; gate++) {
            const int cc = gate * 4 + q;
            const int lane_g = (cc >> 3) * 16 + bgp;
            const int m = (cc & 7) * 4 + idx;
            const float* base = rb + lane_g * 33 + m;
            float s = base[0];
#pragma unroll
            for (int kk = 1; kk < 16; kk++) s += base[kk * 1056];
            z[gate] = s;
        }
        float cvi = 0.0f, cvf = 0.0f, cvg = 0.0f, cvo = 0.0f;
        if (smCvec) {
            cvi = smCvec[b * 16 + q];
            cvf = smCvec[b * 16 + 4 + q];
            cvg = smCvec[b * 16 + 8 + q];
            cvo = smCvec[b * 16 + 12 + q];
        }
        float zi = z[0] + smBias[q]      + cvi;
        float zf = z[1] + smBias[4 + q]  + cvf;
        float zg = z[2] + smBias[8 + q]  + cvg;
        float zo = z[3] + smBias[12 + q] + cvo;
        float co = smC[b * 4 + q];
        float ig = sigf(zi), fg = sigf(zf), gg = tanhf(zg), og = sigf(zo);
        float cn = fg * co + ig * gg;
        float hn = og * tanhf(cn);
        smC[b * 4 + q] = cn;
        __stcg(&gHout[n * BB + b], hn);   // transposed write [d][b]
    }
}

// ============================================================================
// P3: out = sigmoid(h1T @ W_out + b_out). CTA covers 2 cols. 16 warps x 32k.
// lane: bg = lane&15 (b = bg*4..+3), cg = lane>>4 (1 col each). 2 f32x2 accs.
// ============================================================================
__device__ __noinline__ void phase_p3(
    const float* __restrict__ gsrc,
    const float* __restrict__ smWO, const float* __restrict__ smBias,
    float* __restrict__ dout, int t, float* __restrict__ sm, unsigned par0)
{
    const int tid = threadIdx.x;
    const int w = tid >> 5, lane = tid & 31;
    const int bg = lane & 15, cg = lane >> 4;
    const int cbase = blockIdx.x * 2;
    const int wrow0 = w * 32;

    const unsigned smu = smem_u32(sm);
    const unsigned mbar = smu + (OFF_MBAR + w * 2) * 4;
    const unsigned dbase = smu + (OFF_WORK + w * 1024) * 4;

    unsigned long long acc2[2] = {0ull, 0ull};

    if (lane == 0) {
        mbar_expect_tx(mbar, 2048);
        bulk_g2s(dbase, gsrc + w * 32 * BB, 2048, mbar);
    }

    for (int ch = 0; ch < 4; ch++) {
        mbar_wait(mbar, (par0 + ch) & 1);
        if (ch + 1 < 4 && lane == 0) {
            mbar_expect_tx(mbar, 2048);
            bulk_g2s(dbase + ((ch + 1) & 1) * 2048,
                     gsrc + w * 32 * BB + (ch + 1) * 512, 2048, mbar);
        }
        __syncwarp();
        const float* mb = sm + OFF_WORK + w * 1024 + (ch & 1) * 512;
#pragma unroll
        for (int j = 0; j < 8; j++) {
            ulonglong2 aA = *(const ulonglong2*)(mb + j * 64 + bg * 4);
            unsigned long long wp = pack2(smWO[(wrow0 + ch * 8 + j) * 2 + cg]);
            acc2[0] = ffma2(aA.x, wp, acc2[0]);
            acc2[1] = ffma2(aA.y, wp, acc2[1]);
        }
    }

    // partials: per warp [32 lanes][5]; b = bg*4 + m
    float* rb = sm + OFF_WORK;
    __syncthreads();
    rb[w * 160 + lane * 5 + 0] = lo2(acc2[0]);
    rb[w * 160 + lane * 5 + 1] = hi2(acc2[0]);
    rb[w * 160 + lane * 5 + 2] = lo2(acc2[1]);
    rb[w * 160 + lane * 5 + 3] = hi2(acc2[1]);
    __syncthreads();

    if (tid < 128) {
        const int b = tid >> 1, cl = tid & 1;
        const int lane_g = cl * 16 + (b >> 2), m = b & 3;
        const float* base = rb + lane_g * 5 + m;
        float s = base[0];
#pragma unroll
        for (int kk = 1; kk < 16; kk++) s += base[kk * 160];
        float v = sigf(s + smBias[32 + cl]);
        dout[(b * TT + t) * WW + cbase + cl] = v;
        __stcg(&g_prevT[cbase + cl][b], v);   // transposed write
    }
}

// ============================================================================
// Persistent kernel
// ============================================================================
__global__ void __launch_bounds__(TPB, 1)
lstm_persistent_kernel(const float* __restrict__ inputs,
                       const float* __restrict__ rand_prev,
                       const float* __restrict__ init_h,
                       const float* __restrict__ init_c,
                       const float* __restrict__ W_in,
                       const float* __restrict__ b_in,
                       const float* __restrict__ kernels,
                       const float* __restrict__ rec_kernels,
                       const float* __restrict__ biases,
                       const float* __restrict__ W_out,
                       const float* __restrict__ b_out,
                       float* __restrict__ out) {
    extern __shared__ float sm[];
    const int tid = threadIdx.x;
    const int w = tid >> 5;
    const int nbase = blockIdx.x * 4;
    const int cbase = blockIdx.x * 2;
    const int gt = blockIdx.x * TPB + tid;
    const int gstride = NBLK * TPB;

    // mbarrier init (one per warp)
    if (tid < 16) mbar_init(smem_u32(sm) + (OFF_MBAR + tid * 2) * 4, 1);

    // ---- weight preload into smem ----
    for (int idx = tid; idx < 512 * 16; idx += TPB) {
        int row = idx >> 4, c = idx & 15, g = c >> 2, q = c & 3;
        sm[OFF_W0 + (256 + row) * 16 + c] = rec_kernels[row * G4D + g * DD + nbase + q];
    }
    for (int idx = tid; idx < 1024 * 16; idx += TPB) {
        int row = idx >> 4, c = idx & 15, g = c >> 2, q = c & 3;
        float v = (row < 512)
            ? kernels[DD * G4D + row * G4D + g * DD + nbase + q]
            : rec_kernels[DD * G4D + (row - 512) * G4D + g * DD + nbase + q];
        sm[OFF_W1 + idx] = v;
    }
    for (int idx = tid; idx < 512 * 2; idx += TPB) {
        int k = idx >> 1, c = idx & 1;
        sm[OFF_WOUT + idx] = W_out[k * WW + cbase + c];
    }
    if (tid < 16) {
        int g = tid >> 2, q = tid & 3;
        sm[OFF_BIAS + tid] = biases[g * DD + nbase + q];
    } else if (tid < 32) {
        int c = tid - 16, g = c >> 2, q = c & 3;
        sm[OFF_BIAS + tid] = biases[G4D + g * DD + nbase + q];
    } else if (tid < 34) {
        sm[OFF_BIAS + tid] = b_out[cbase + tid - 32];
    }
    for (int idx = tid; idx < 512; idx += TPB) {
        int l = idx >> 8, r = idx & 255, b = r >> 2, q = r & 3;
        sm[OFF_CST + idx] = init_c[(l * BB + b) * DD + nbase + q];
    }

    // ---- global state init (transposed; every launch — graph replays) ----
    if (tid == 0) g_flags[blockIdx.x] = 0;
    for (int i = gt; i < 2 * DD * BB; i += gstride) {
        int l = i >> 15, d = (i >> 6) & (DD - 1), b = i & 63;
        g_hT[0][l][d][b] = init_h[(l * BB + b) * DD + d];
    }
    for (int i = gt; i < WW * BB; i += gstride) {
        int k = i >> 6, b = i & 63;
        g_prevT[k][b] = rand_prev[b * WW + k];
    }
    for (int i = gt; i < BB * DD; i += gstride) {
        const int b = i >> 9, dc = i & (DD - 1);
        const float* cn = inputs + b * FF;
        float s = b_in[dc];
#pragma unroll 4
        for (int k = 0; k < FF; k++)
            s = fmaf(cn[k], W_in[(WW + k) * DD + dc], s);
        (&g_cbias[0][0])[i] = s;
    }
    grid_barrier_atomic();

    // ---- M0 = W_in[0:256] @ K0 -> smem W0 rows 0..255 ----
    for (int idx = tid; idx < 256 * 16; idx += TPB) {
        int r = idx >> 4, c = idx & 15, g = c >> 2, q = c & 3;
        const int col = g * DD + nbase + q;
        float s = 0.0f;
#pragma unroll 8
        for (int d = 0; d < DD; d++)
            s = fmaf(W_in[r * DD + d], kernels[d * G4D + col], s);
        sm[OFF_W0 + r * 16 + c] = s;
    }
    // ---- cvec = cbias @ K0 ----
    for (int idx = tid; idx < BB * 16; idx += TPB) {
        int b = idx >> 4, c = idx & 15, g = c >> 2, q = c & 3;
        const int col = g * DD + nbase + q;
        float s = 0.0f;
#pragma unroll 8
        for (int d = 0; d < DD; d++)
            s = fmaf(g_cbias[b][d], kernels[d * G4D + col], s);
        sm[OFF_CVEC + b * 16 + c] = s;
    }
    __syncthreads();

    // ---- balanced L0 slice parameters: 48 rows/warp (6 chunks), boundary 256 ----
    const int l0_row0 = w * 48;
    int chB0 = (256 - l0_row0) >> 3;
    if (chB0 < 0) chB0 = 0;
    if (chB0 > 6) chB0 = 6;
    int offB0 = l0_row0 + chB0 * 8 - 256;
    if (offB0 < 0) offB0 = 0;
    const float* l0A = &g_prevT[0][0] + l0_row0 * BB;

    unsigned seq = 0, mcount = 0;
    for (int t = 0; t < TT; t++) {
        const int p = t & 1;

        // L0: rows < 256 from prevT, >= 256 from h0T prev; uniform 6 chunks/warp
        {
            const float* l0B = &g_hT[p][0][0][0] + offB0 * BB;
            phase_L(l0A, l0B, chB0, 6, l0_row0,
                    sm + OFF_W0, sm + OFF_BIAS, sm + OFF_CVEC,
                    sm + OFF_CST, &g_hT[1 - p][0][0][0], sm, mcount);
            mcount += 6;
        }
        flag_barrier(++seq);

        // L1: A = [h0T new (512k) | h1T prev (512k)], uniform 64k/warp
        {
            const float* gsrc = (w < 8)
                ? (&g_hT[1 - p][0][0][0] + w * 64 * BB)
                : (&g_hT[p][1][0][0] + (w - 8) * 64 * BB);
            phase_L(gsrc, gsrc, 8, 8, w * 64,
                    sm + OFF_W1, sm + OFF_BIAS + 16, (const float*)0,
                    sm + OFF_CST + 256, &g_hT[1 - p][1][0][0], sm, mcount);
            mcount += 8;
        }
        flag_barrier(++seq);

        // P3: h1T new @ W_out
        phase_p3(&g_hT[1 - p][1][0][0], sm + OFF_WOUT, sm + OFF_BIAS,
                 out, t, sm, mcount);
        mcount += 4;
        flag_barrier(++seq);
    }
}

extern "C" void kernel_launch(void* const* d_in, const int* in_sizes, int n_in,
                              void* d_out, int out_size) {
    const float* inputs      = (const float*)d_in[0];
    const float* rand_prev   = (const float*)d_in[1];
    const float* init_h      = (const float*)d_in[2];
    const float* init_c      = (const float*)d_in[3];
    const float* W_in        = (const float*)d_in[4];
    const float* b_in        = (const float*)d_in[5];
    const float* kernels     = (const float*)d_in[6];
    const float* rec_kernels = (const float*)d_in[7];
    const float* biases      = (const float*)d_in[8];
    const float* W_out       = (const float*)d_in[9];
    const float* b_out       = (const float*)d_in[10];
    float* out = (float*)d_out;

    static int attr_done = 0;
    if (!attr_done) {
        cudaFuncSetAttribute(lstm_persistent_kernel,
                             cudaFuncAttributeMaxDynamicSharedMemorySize, SMEM_BYTES);
        attr_done = 1;
    }
    lstm_persistent_kernel<<<NBLK, TPB, SMEM_BYTES>>>(
        inputs, rand_prev, init_h, init_c, W_in, b_in, kernels, rec_kernels,
        biases, W_out, b_out, out);
}